// round 10
// baseline (speedup 1.0000x reference)
#include <cuda_runtime.h>
#include <cstdint>

#define TILE_N 16
#define THREADS 256
#define XS 1028            // x_s row stride (words) ≡ 4 (mod 32): conflict-free frag reads
#define WS 68              // w_s row stride ≡ 4 (mod 32)
#define OST_MAX 452        // out-stage row stride for lo=3 (64*7+4)

__device__ __forceinline__ unsigned f2tf_rna(float f) {
    unsigned u; asm("cvt.rna.tf32.f32 %0, %1;" : "=r"(u) : "f"(f)); return u;
}

__device__ __forceinline__ void cp16(float* dst, const float* src) {
    unsigned d = (unsigned)__cvta_generic_to_shared(dst);
    asm volatile("cp.async.cg.shared.global [%0], [%1], 16;" :: "r"(d), "l"(src));
}
__device__ __forceinline__ void cp_commit() {
    asm volatile("cp.async.commit_group;" ::: "memory");
}
__device__ __forceinline__ void cp_wait0() {
    asm volatile("cp.async.wait_group 0;" ::: "memory");
}

#define MMA8(C, A0, A1, A2, A3, B0, B1)                                        \
    asm volatile("mma.sync.aligned.m16n8k8.row.col.f32.tf32.tf32.f32 "         \
        "{%0,%1,%2,%3}, {%4,%5,%6,%7}, {%8,%9}, {%0,%1,%2,%3};"                \
        : "+f"((C)[0]), "+f"((C)[1]), "+f"((C)[2]), "+f"((C)[3])               \
        : "r"(A0), "r"(A1), "r"(A2), "r"(A3), "r"(B0), "r"(B1))

__global__ __launch_bounds__(THREADS, 2)
void tp_kernel(const float* __restrict__ x, const float* __restrict__ W,
               const float* __restrict__ hzero, const float* __restrict__ hpos,
               const float* __restrict__ hneg, float* __restrict__ out)
{
    extern __shared__ float smem[];
    float* x_s = smem;                          // TILE_N * XS
    float* w_s = smem + TILE_N * XS;            // 64 * WS (single buffer, reg-prefetched)
    float* o_s = w_s + 64 * WS;                 // TILE_N * OST_MAX

    const int tid = threadIdx.x;
    const long long n0 = (long long)blockIdx.x * TILE_N;

    // ---- prologue: x tile via cp.async; W0 -> regs -> smem; W1 -> regs ----
    {
        const float* xg = x + n0 * 1024;
        #pragma unroll
        for (int q0 = 0; q0 < 16; ++q0) {
            int q = tid + q0 * THREADS;                       // 4096 float4
            cp16(x_s + (q >> 8) * XS + ((q & 255) << 2), xg + q * 4);
        }
        cp_commit();
    }
    const float4* W4 = (const float4*)W;
    float4 wreg[4];
    #pragma unroll
    for (int q0 = 0; q0 < 4; ++q0) wreg[q0] = __ldg(W4 + tid + q0 * THREADS);
    #pragma unroll
    for (int q0 = 0; q0 < 4; ++q0) {
        int q = tid + q0 * THREADS;
        *(float4*)(w_s + (q >> 4) * WS + ((q & 15) << 2)) = wreg[q0];
    }
    #pragma unroll
    for (int q0 = 0; q0 < 4; ++q0) wreg[q0] = __ldg(W4 + 1024 + tid + q0 * THREADS);
    cp_wait0();
    __syncthreads();              // x_s and w_s(W0) visible

    const int warp = tid >> 5, lane = tid & 31;
    const int wk = warp & 1;                      // K-half
    const int wn = warp >> 1;                     // 4 N-warps
    const int g  = lane >> 2, t4 = lane & 3;
    const int r0 = g;
    const float* xrow0 = x_s + r0 * XS;
    const float* xrow1 = xrow0 + 8 * XS;

    #pragma unroll
    for (int oi = 0; oi < 4; ++oi) {
        const int lo = oi, so = 2 * oi + 1;
        const int offo = 64 * oi * oi;
        const int ost = 64 * so + 4;

        float acc[2][7][4];
        #pragma unroll
        for (int nt = 0; nt < 2; ++nt)
            #pragma unroll
            for (int co = 0; co <= 2 * oi; ++co) {
                acc[nt][co][0] = 0.f; acc[nt][co][1] = 0.f;
                acc[nt][co][2] = 0.f; acc[nt][co][3] = 0.f;
            }

        #pragma unroll
        for (int ii = 0; ii < 4; ++ii) {
            const int li = ii, si = 2 * ii + 1;
            const int base = 64 * ii * ii;
            const int p = (oi << 2) + ii;

            // ---- B (W) fragments from w_s (holds W_p), cvt at frag load ----
            unsigned bw[2][4][2];
            {
                const float* wb = w_s + (wn * 16 + g) * WS + 32 * wk + t4;
                #pragma unroll
                for (int nt = 0; nt < 2; ++nt)
                    #pragma unroll
                    for (int s = 0; s < 4; ++s) {
                        bw[nt][s][0] = f2tf_rna(wb[nt * 8 * WS + 8 * s]);
                        bw[nt][s][1] = f2tf_rna(wb[nt * 8 * WS + 8 * s + 4]);
                    }
            }
            __syncthreads();      // all warps done reading w_s (W_p)
            if (p < 15) {         // w_s <- W_{p+1} from prefetch regs
                #pragma unroll
                for (int q0 = 0; q0 < 4; ++q0) {
                    int q = tid + q0 * THREADS;
                    *(float4*)(w_s + (q >> 4) * WS + ((q & 15) << 2)) = wreg[q0];
                }
            }
            __syncthreads();      // w_s(W_{p+1}) visible
            if (p < 14) {         // prefetch W_{p+2} into regs; hidden by compute below
                #pragma unroll
                for (int q0 = 0; q0 < 4; ++q0)
                    wreg[q0] = __ldg(W4 + (p + 2) * 1024 + tid + q0 * THREADS);
            }

            const int kb = 32 * wk * si;              // K-half channel offset
            const float* xa0 = xrow0 + base + li + kb;
            const float* xa1 = xrow1 + base + li + kb;
            const float h0 = __ldg(hzero + p);

            // ---- m = 0 vgemm (A = fp32 bits, HW truncates to tf32) ----
            #pragma unroll
            for (int s = 0; s < 4; ++s) {
                int c0 = (t4 + 8 * s) * si, c1 = c0 + 4 * si;
                unsigned a0 = __float_as_uint(h0 * xa0[c0]);
                unsigned a1 = __float_as_uint(h0 * xa1[c0]);
                unsigned a2 = __float_as_uint(h0 * xa0[c1]);
                unsigned a3 = __float_as_uint(h0 * xa1[c1]);
                MMA8(acc[0][lo], a0, a1, a2, a3, bw[0][s][0], bw[0][s][1]);
                MMA8(acc[1][lo], a0, a1, a2, a3, bw[1][s][0], bw[1][s][1]);
            }

            // ---- m >= 1: fused (+m, -m) pair sharing x loads ----
            #pragma unroll
            for (int m = 1; m <= oi; ++m) {
                if (ii >= m) {
                    const float hp = __ldg(hpos + p * 3 + m - 1);
                    const float hn = __ldg(hneg + p * 3 + m - 1);
                    #pragma unroll
                    for (int s = 0; s < 4; ++s) {
                        int c0 = (t4 + 8 * s) * si, c1 = c0 + 4 * si;
                        float xp00 = xa0[c0 + m], xn00 = xa0[c0 - m];
                        float xp10 = xa1[c0 + m], xn10 = xa1[c0 - m];
                        float xp01 = xa0[c1 + m], xn01 = xa0[c1 - m];
                        float xp11 = xa1[c1 + m], xn11 = xa1[c1 - m];
                        unsigned u0 = __float_as_uint(hp * xp00 + hn * xn00);
                        unsigned u1 = __float_as_uint(hp * xp10 + hn * xn10);
                        unsigned u2 = __float_as_uint(hp * xp01 + hn * xn01);
                        unsigned u3 = __float_as_uint(hp * xp11 + hn * xn11);
                        unsigned v0 = __float_as_uint(hp * xn00 - hn * xp00);
                        unsigned v1 = __float_as_uint(hp * xn10 - hn * xp10);
                        unsigned v2 = __float_as_uint(hp * xn01 - hn * xp01);
                        unsigned v3 = __float_as_uint(hp * xn11 - hn * xp11);
                        MMA8(acc[0][lo + m], u0, u1, u2, u3, bw[0][s][0], bw[0][s][1]);
                        MMA8(acc[1][lo + m], u0, u1, u2, u3, bw[1][s][0], bw[1][s][1]);
                        MMA8(acc[0][lo - m], v0, v1, v2, v3, bw[0][s][0], bw[0][s][1]);
                        MMA8(acc[1][lo - m], v0, v1, v2, v3, bw[1][s][0], bw[1][s][1]);
                    }
                }
            }
        }

        // ---- epilogue: K-half reduce through o_s, then coalesced float4 stores ----
        if (wk == 0) {
            #pragma unroll
            for (int nt = 0; nt < 2; ++nt) {
                int o0 = wn * 16 + nt * 8 + 2 * t4;
                #pragma unroll
                for (int co = 0; co <= 2 * oi; ++co) {
                    float* d0 = o_s + r0 * ost + o0 * so + co;
                    float* d1 = d0 + 8 * ost;
                    d0[0]  = acc[nt][co][0];
                    d0[so] = acc[nt][co][1];
                    d1[0]  = acc[nt][co][2];
                    d1[so] = acc[nt][co][3];
                }
            }
        }
        __syncthreads();
        if (wk == 1) {
            #pragma unroll
            for (int nt = 0; nt < 2; ++nt) {
                int o0 = wn * 16 + nt * 8 + 2 * t4;
                #pragma unroll
                for (int co = 0; co <= 2 * oi; ++co) {
                    float* d0 = o_s + r0 * ost + o0 * so + co;
                    float* d1 = d0 + 8 * ost;
                    d0[0]  += acc[nt][co][0];
                    d0[so] += acc[nt][co][1];
                    d1[0]  += acc[nt][co][2];
                    d1[so] += acc[nt][co][3];
                }
            }
        }
        __syncthreads();
        {
            const int nf4 = 16 * so;
            for (int q = tid; q < TILE_N * nf4; q += THREADS) {
                int r = q / nf4, c = q - r * nf4;
                float4 v = *(const float4*)(o_s + r * ost + (c << 2));
                *(float4*)(out + (n0 + r) * 1024 + offo + (c << 2)) = v;
            }
        }
        __syncthreads();   // o_s reusable; also fences next oi's w_s cycle
    }
}

extern "C" void kernel_launch(void* const* d_in, const int* in_sizes, int n_in,
                              void* d_out, int out_size) {
    const float* x  = (const float*)d_in[0];
    const float* w  = (const float*)d_in[1];
    const float* hz = (const float*)d_in[2];
    const float* hp = (const float*)d_in[3];
    const float* hn = (const float*)d_in[4];
    float* out = (float*)d_out;

    const int n = in_sizes[0] / 1024;              // 65536
    const int grid = n / TILE_N;                   // 4096
    const int smem_bytes = (TILE_N * XS + 64 * WS + TILE_N * OST_MAX) * 4; // 112128 B

    cudaFuncSetAttribute(tp_kernel, cudaFuncAttributeMaxDynamicSharedMemorySize, smem_bytes);
    tp_kernel<<<grid, THREADS, smem_bytes>>>(x, w, hz, hp, hn, out);
}

// round 12
// speedup vs baseline: 1.1905x; 1.1905x over previous
#include <cuda_runtime.h>
#include <cuda_fp16.h>
#include <cstdint>

#define TILE_N 32
#define THREADS 256
#define XH 1032            // x_h row stride in halves (516 words ≡ 4 mod 32 -> conflict-free A frags)
#define XSF 1028           // scratch fp32 row stride (words)
#define WS 72              // w_s row stride (floats) ≡ 8 mod 32 -> conflict-free LDS.64 B reads
#define WBUF (64 * WS)     // 4608 floats per W buffer
#define OST_MAX 452        // out-stage row stride for lo=3 (64*7+4)

__device__ __forceinline__ unsigned pack_h2(float lo, float hi) {
    unsigned d; asm("cvt.rn.f16x2.f32 %0, %1, %2;" : "=r"(d) : "f"(hi), "f"(lo)); return d;
}
__device__ __forceinline__ void cp16(float* dst, const float* src) {
    unsigned d = (unsigned)__cvta_generic_to_shared(dst);
    asm volatile("cp.async.cg.shared.global [%0], [%1], 16;" :: "r"(d), "l"(src));
}
__device__ __forceinline__ void cp_commit() {
    asm volatile("cp.async.commit_group;" ::: "memory");
}
__device__ __forceinline__ void cp_wait0() {
    asm volatile("cp.async.wait_group 0;" ::: "memory");
}
__device__ __forceinline__ void cp_wait1() {
    asm volatile("cp.async.wait_group 1;" ::: "memory");
}

#define MMA16(C, A0, A1, A2, A3, B0, B1)                                       \
    asm volatile("mma.sync.aligned.m16n8k16.row.col.f32.f16.f16.f32 "          \
        "{%0,%1,%2,%3}, {%4,%5,%6,%7}, {%8,%9}, {%0,%1,%2,%3};"                \
        : "+f"((C)[0]), "+f"((C)[1]), "+f"((C)[2]), "+f"((C)[3])               \
        : "r"(A0), "r"(A1), "r"(A2), "r"(A3), "r"(B0), "r"(B1))

// raw channel MMA: t[2][4] += x[channel] @ W  (A = fp16 half2 straight from x_h)
#define RAW_CH(T, CW)                                                           \
    do {                                                                        \
        _Pragma("unroll")                                                       \
        for (int ks = 0; ks < 4; ++ks) {                                        \
            unsigned a0 = xw0[(CW) + 8 * ks],     a1 = xw1[(CW) + 8 * ks];      \
            unsigned a2 = xw0[(CW) + 8 * ks + 4], a3 = xw1[(CW) + 8 * ks + 4];  \
            MMA16(T[0], a0, a1, a2, a3, bw[0][ks][0], bw[0][ks][1]);            \
            MMA16(T[1], a0, a1, a2, a3, bw[1][ks][0], bw[1][ks][1]);            \
        }                                                                       \
    } while (0)

__global__ __launch_bounds__(THREADS, 1)
void tp_kernel(const float* __restrict__ x, const float* __restrict__ W,
               const float* __restrict__ hzero, const float* __restrict__ hpos,
               const float* __restrict__ hneg, float* __restrict__ out)
{
    extern __shared__ float smem[];
    __half* x_h = (__half*)smem;                        // 32*XH halves = 66048 B
    float*  w_s = (float*)((char*)smem + 32 * XH * 2);  // 2*WBUF floats = 36864 B
    float*  o_s = w_s + 2 * WBUF;                       // 32*OST_MAX floats = 57856 B
    float*  scr = w_s + WBUF;                           // transpose scratch (wbuf1 + o_s region)

    const int tid = threadIdx.x;
    const long long n0 = (long long)blockIdx.x * TILE_N;
    const float* xg = x + n0 * 1024;

    // ---- prologue: W0 cp.async; x via pipelined 8-row chunks -> fp16 transpose ----
    {
        #pragma unroll
        for (int q0 = 0; q0 < 4; ++q0) {
            int q = tid + q0 * THREADS;
            cp16(w_s + (q >> 4) * WS + ((q & 15) << 2), W + q * 4);
        }
        cp_commit();                                   // group: W0
        // chunk 0
        #pragma unroll
        for (int q0 = 0; q0 < 8; ++q0) {
            int q = tid + q0 * THREADS;                // 2048 float4 per chunk
            cp16(scr + (q >> 8) * XSF + ((q & 255) << 2), xg + q * 4);
        }
        cp_commit();                                   // group: chunk 0

        for (int k = 0; k < 4; ++k) {
            if (k < 3) {
                float* dst = scr + ((k + 1) & 1) * (8 * XSF);
                const float* src = xg + (k + 1) * 8192;
                #pragma unroll
                for (int q0 = 0; q0 < 8; ++q0) {
                    int q = tid + q0 * THREADS;
                    cp16(dst + (q >> 8) * XSF + ((q & 255) << 2), src + q * 4);
                }
                cp_commit();
                cp_wait1();
            } else {
                cp_wait0();
            }
            __syncthreads();                           // chunk k visible to all
            const float* sb = scr + (k & 1) * (8 * XSF);
            #pragma unroll
            for (int bi = 0; bi < 4; ++bi) {
                const int si = 2 * bi + 1, basef = 64 * bi * bi;
                const int cnt = 512 * si;              // 8 rows * 64 * si
                for (int q = tid; q < cnt; q += THREADS) {
                    int i = q & 63, rc = q >> 6;
                    int c = rc % si, r = rc / si;
                    float v = sb[r * XSF + basef + i * si + c];
                    x_h[(8 * k + r) * XH + basef + c * 64 + i] = __float2half_rn(v);
                }
            }
        }
    }

    const int warp = tid >> 5, lane = tid & 31;
    const int wm = warp >> 2, wn = warp & 3;       // 2 (M) x 4 (N) warp grid
    const int g  = lane >> 2, t4 = lane & 3;
    const int r0 = wm * 16 + g;
    const unsigned* xw0 = (const unsigned*)x_h + r0 * (XH / 2) + t4;   // word-indexed
    const unsigned* xw1 = xw0 + 8 * (XH / 2);

    #pragma unroll
    for (int oi = 0; oi < 4; ++oi) {
        const int lo = oi, so = 2 * oi + 1;
        const int offo = 64 * oi * oi;
        const int ost = 64 * so + 4;

        float acc[2][7][4];
        #pragma unroll
        for (int nt = 0; nt < 2; ++nt)
            #pragma unroll
            for (int co = 0; co <= 2 * oi; ++co) {
                acc[nt][co][0] = 0.f; acc[nt][co][1] = 0.f;
                acc[nt][co][2] = 0.f; acc[nt][co][3] = 0.f;
            }

        #pragma unroll
        for (int ii = 0; ii < 4; ++ii) {
            const int bh2 = 32 * ii * ii;              // block base in words (halves/2)
            const int p = (oi << 2) + ii;

            cp_wait0();          // W_p staged (this thread)
            __syncthreads();     // all copies visible; prior path done with both buffers

            if (p < 15) {        // prefetch next path's W into the other buffer
                const float* Wn = W + (p + 1) * 4096;
                float* wd = w_s + ((p + 1) & 1) * WBUF;
                #pragma unroll
                for (int q0 = 0; q0 < 4; ++q0) {
                    int q = tid + q0 * THREADS;
                    cp16(wd + (q >> 4) * WS + ((q & 15) << 2), Wn + q * 4);
                }
                cp_commit();
            }

            // ---- B (W) fragments: fp32 LDS.64 pair -> packed half2 ----
            unsigned bw[2][4][2];
            {
                const float* wb = w_s + (p & 1) * WBUF + (wn * 16 + g) * WS + 2 * t4;
                #pragma unroll
                for (int nt = 0; nt < 2; ++nt)
                    #pragma unroll
                    for (int ks = 0; ks < 4; ++ks) {
                        float2 f0 = *(const float2*)(wb + nt * 8 * WS + 16 * ks);
                        float2 f1 = *(const float2*)(wb + nt * 8 * WS + 16 * ks + 8);
                        bw[nt][ks][0] = pack_h2(f0.x, f0.y);
                        bw[nt][ks][1] = pack_h2(f1.x, f1.y);
                    }
            }

            const float h0 = __ldg(hzero + p);

            // ---- m = 0: raw x[li] @ W, scale by h0 into acc ----
            {
                float t[2][4];
                #pragma unroll
                for (int nt = 0; nt < 2; ++nt)
                    t[nt][0] = t[nt][1] = t[nt][2] = t[nt][3] = 0.f;
                const int cw = bh2 + ii * 32;          // channel c = li
                RAW_CH(t, cw);
                #pragma unroll
                for (int nt = 0; nt < 2; ++nt)
                    #pragma unroll
                    for (int j = 0; j < 4; ++j)
                        acc[nt][lo][j] = fmaf(h0, t[nt][j], acc[nt][lo][j]);
            }

            // ---- m >= 1: raw xp@W, xn@W; rotate once per m-group in fp32 ----
            #pragma unroll
            for (int m = 1; m <= oi; ++m) {
                if (ii >= m) {
                    float tp[2][4], tn[2][4];
                    #pragma unroll
                    for (int nt = 0; nt < 2; ++nt) {
                        tp[nt][0] = tp[nt][1] = tp[nt][2] = tp[nt][3] = 0.f;
                        tn[nt][0] = tn[nt][1] = tn[nt][2] = tn[nt][3] = 0.f;
                    }
                    const int cwp = bh2 + (ii + m) * 32;   // channel li+m
                    const int cwn = bh2 + (ii - m) * 32;   // channel li-m
                    RAW_CH(tp, cwp);
                    RAW_CH(tn, cwn);
                    const float hp = __ldg(hpos + p * 3 + m - 1);
                    const float hn = __ldg(hneg + p * 3 + m - 1);
                    #pragma unroll
                    for (int nt = 0; nt < 2; ++nt)
                        #pragma unroll
                        for (int j = 0; j < 4; ++j) {
                            acc[nt][lo + m][j] = fmaf(hp, tp[nt][j],
                                                 fmaf(hn, tn[nt][j], acc[nt][lo + m][j]));
                            acc[nt][lo - m][j] = fmaf(hp, tn[nt][j],
                                                 fmaf(-hn, tp[nt][j], acc[nt][lo - m][j]));
                        }
                }
            }
        }

        // ---- epilogue: regs -> interleaved stage -> coalesced float4 global ----
        // (prior oi's o_s reads fenced by this oi's ii=0 barrier)
        #pragma unroll
        for (int nt = 0; nt < 2; ++nt) {
            int o0 = wn * 16 + nt * 8 + 2 * t4;
            #pragma unroll
            for (int co = 0; co <= 2 * oi; ++co) {
                float* d0 = o_s + r0 * ost + o0 * so + co;
                float* d1 = d0 + 8 * ost;
                d0[0]  = acc[nt][co][0];
                d0[so] = acc[nt][co][1];
                d1[0]  = acc[nt][co][2];
                d1[so] = acc[nt][co][3];
            }
        }
        __syncthreads();
        {
            const int nf4 = 16 * so;
            for (int q = tid; q < TILE_N * nf4; q += THREADS) {
                int r = q / nf4, c = q - r * nf4;
                float4 v = *(const float4*)(o_s + r * ost + (c << 2));
                *(float4*)(out + (n0 + r) * 1024 + offo + (c << 2)) = v;
            }
        }
    }
}

extern "C" void kernel_launch(void* const* d_in, const int* in_sizes, int n_in,
                              void* d_out, int out_size) {
    const float* x  = (const float*)d_in[0];
    const float* w  = (const float*)d_in[1];
    const float* hz = (const float*)d_in[2];
    const float* hp = (const float*)d_in[3];
    const float* hn = (const float*)d_in[4];
    float* out = (float*)d_out;

    const int n = in_sizes[0] / 1024;              // 65536
    const int grid = n / TILE_N;                   // 2048
    const int smem_bytes = 32 * XH * 2 + 2 * WBUF * 4 + TILE_N * OST_MAX * 4; // 160768 B

    cudaFuncSetAttribute(tp_kernel, cudaFuncAttributeMaxDynamicSharedMemorySize, smem_bytes);
    tp_kernel<<<grid, THREADS, smem_bytes>>>(x, w, hz, hp, hn, out);
}